// round 7
// baseline (speedup 1.0000x reference)
#include <cuda_runtime.h>
#include <math.h>

#define NN   768
#define HH   4
#define DDIM 3
#define HDIM 64
#define HID  64
#define HC   80
#define DE   164
#define NT   12      // 768 / 64 j-tiles

// ---------------- shared memory layout (float offsets) ----------------
#define OFF_W0   0        // 164*64 = 10496
#define OFF_W1   10496    // 4096
#define OFF_WX0  14592    // 4096
#define OFF_WX1  18688    // 4096
#define OFF_WX2  22784    // 64*4 = 256
#define OFF_B0   23040    // 64
#define OFF_B1   23104    // 64
#define OFF_BX0  23168    // 64
#define OFF_BX1  23232    // 64
#define OFF_BX2  23296    // 4
#define OFF_WINF 23300    // 64
#define OFF_HIS  23364    // 80
#define OFF_XI   23444    // 12
#define OFF_ES   23456    // 64
#define OFF_EINT 23520    // 164*64 = 10496  (16B aligned)
#define OFF_BUFA 34016    // 64*64 = 4096
#define OFF_BUFB 38112    // 64*64 = 4096
#define OFF_XJS  42208    // 64*12 = 768
#define SMEM_FLOATS 42976
#define SMEM_BYTES  (SMEM_FLOATS * 4)   // 171904 bytes

// ---------------- device scratch (no allocs allowed) ----------------
__device__ float g_hcT[HC * NN];     // transposed h_concat: [80][768]
__device__ float g_mi[NN * HID];     // unnormalized m_i sums

// ---------------- helpers ----------------
__device__ __forceinline__ float sigmoidf_(float z) { return 1.0f / (1.0f + __expf(-z)); }
__device__ __forceinline__ float siluf_(float z)    { return z / (1.0f + __expf(-z)); }

__device__ __forceinline__ unsigned long long pk2(float lo, float hi) {
    unsigned long long r;
    asm("mov.b64 %0, {%1, %2};" : "=l"(r) : "f"(lo), "f"(hi));
    return r;
}
__device__ __forceinline__ void ffma2(unsigned long long &d, unsigned long long a, unsigned long long b) {
    asm("fma.rn.f32x2 %0, %1, %2, %0;" : "+l"(d) : "l"(a), "l"(b));
}
__device__ __forceinline__ void unpk2(float &lo, float &hi, unsigned long long p) {
    asm("mov.b64 {%0, %1}, %2;" : "=f"(lo), "=f"(hi) : "l"(p));
}

// GEMM: C[j=4ty+r][c=4tx+cc] = act( sum_k A[k][j] * B[k][c] + bias[c] ),
// stored transposed into sm[OUTOFF + c*64 + j].  A,B are [K][64] in smem.
#define GEMM_T(AOFF, BOFF, KK, BIASOFF, OUTOFF, MASKJ)                              \
  do {                                                                              \
    unsigned long long acc00=0ull,acc01=0ull,acc10=0ull,acc11=0ull;                 \
    unsigned long long acc20=0ull,acc21=0ull,acc30=0ull,acc31=0ull;                 \
    _Pragma("unroll 4")                                                             \
    for (int k = 0; k < (KK); k++) {                                                \
      float4 av = *(const float4*)&sm[(AOFF) + k*64 + ty4];                         \
      float4 bv = *(const float4*)&sm[(BOFF) + k*64 + tx4];                         \
      unsigned long long b01 = pk2(bv.x, bv.y);                                     \
      unsigned long long b23 = pk2(bv.z, bv.w);                                     \
      unsigned long long aa;                                                        \
      aa = pk2(av.x, av.x); ffma2(acc00, aa, b01); ffma2(acc01, aa, b23);           \
      aa = pk2(av.y, av.y); ffma2(acc10, aa, b01); ffma2(acc11, aa, b23);           \
      aa = pk2(av.z, av.z); ffma2(acc20, aa, b01); ffma2(acc21, aa, b23);           \
      aa = pk2(av.w, av.w); ffma2(acc30, aa, b01); ffma2(acc31, aa, b23);           \
    }                                                                               \
    float vals[4][4];                                                               \
    unpk2(vals[0][0], vals[0][1], acc00); unpk2(vals[0][2], vals[0][3], acc01);     \
    unpk2(vals[1][0], vals[1][1], acc10); unpk2(vals[1][2], vals[1][3], acc11);     \
    unpk2(vals[2][0], vals[2][1], acc20); unpk2(vals[2][2], vals[2][3], acc21);     \
    unpk2(vals[3][0], vals[3][1], acc30); unpk2(vals[3][2], vals[3][3], acc31);     \
    _Pragma("unroll")                                                               \
    for (int r = 0; r < 4; r++) {                                                   \
      int jloc = ty4 + r;                                                           \
      _Pragma("unroll")                                                             \
      for (int c = 0; c < 4; c++) {                                                 \
        int cc = tx4 + c;                                                           \
        float z = vals[r][c] + sm[(BIASOFF) + cc];                                  \
        float o = siluf_(z);                                                        \
        if (jloc == (MASKJ)) o = 0.0f;                                              \
        sm[(OUTOFF) + cc*64 + jloc] = o;                                            \
      }                                                                             \
    }                                                                               \
  } while (0)

// ---------------- kernel A: per-node features, transposed ----------------
__global__ void prep_kernel(const float* __restrict__ x, const float* __restrict__ h) {
    int n = blockIdx.x;
    int t = threadIdx.x;   // 0..79
    float v;
    if (t < 64) {
        v = h[n * HDIM + t];
    } else {
        int p = t - 64;          // p = i*4 + j  (matches reshape(n, H*H))
        int pi = p >> 2, pj = p & 3;
        float s = 0.0f;
#pragma unroll
        for (int d = 0; d < DDIM; d++) {
            float df = x[(n * HH + pj) * DDIM + d] - x[(n * HH + pi) * DDIM + d];
            s += df * df;
        }
        v = s;
    }
    g_hcT[t * NN + n] = v;
}

// ---------------- kernel B: all pairs for one node i per block ----------------
__global__ void __launch_bounds__(256, 1) pair_kernel(
    const float* __restrict__ x,
    const float* __restrict__ w0,  const float* __restrict__ b0,
    const float* __restrict__ w1,  const float* __restrict__ b1,
    const float* __restrict__ winf, const float* __restrict__ binf,
    const float* __restrict__ wx0, const float* __restrict__ bx0,
    const float* __restrict__ wx1, const float* __restrict__ bx1,
    const float* __restrict__ wx2, const float* __restrict__ bx2,
    float* __restrict__ xout)
{
    extern __shared__ float sm[];
    const int tid = threadIdx.x;
    const int i   = blockIdx.x;
    const int ty4 = (tid >> 4) << 2;   // 0..60, output j rows
    const int tx4 = (tid & 15) << 2;   // 0..60, output c cols

    // ---- load weights / biases into smem ----
    for (int idx = tid; idx < DE * HID; idx += 256) sm[OFF_W0 + idx] = w0[idx];
    for (int idx = tid; idx < HID * HID; idx += 256) {
        sm[OFF_W1  + idx] = w1[idx];
        sm[OFF_WX0 + idx] = wx0[idx];
        sm[OFF_WX1 + idx] = wx1[idx];
    }
    for (int idx = tid; idx < HID * HH; idx += 256) sm[OFF_WX2 + idx] = wx2[idx];
    if (tid < 64) {
        sm[OFF_B0   + tid] = b0[tid];
        sm[OFF_B1   + tid] = b1[tid];
        sm[OFF_BX0  + tid] = bx0[tid];
        sm[OFF_BX1  + tid] = bx1[tid];
        sm[OFF_WINF + tid] = winf[tid];
    }
    if (tid < 4)  sm[OFF_BX2 + tid] = bx2[tid];
    if (tid < 80) sm[OFF_HIS + tid] = g_hcT[tid * NN + i];
    if (tid < 12) sm[OFF_XI  + tid] = x[i * 12 + tid];
    const float binf_r = binf[0];
    __syncthreads();

    // constant part of EinT: rows 84..163 = h_concat[i], same for every j
    for (int idx = tid; idx < 80 * 64; idx += 256) {
        int t = idx >> 6, jj = idx & 63;
        sm[OFF_EINT + (84 + t) * 64 + jj] = sm[OFF_HIS + t];
    }

    float mi_acc = 0.0f;             // owned by tid<64 (c = tid)
    float sh0 = 0.f, sh1 = 0.f, sh2 = 0.f;   // shift partials for (jj_me, hh_me)
    const int jj_me = tid & 63;
    const int hh_me = tid >> 6;

    for (int tile = 0; tile < NT; tile++) {
        const int j0 = tile * 64;
        __syncthreads();   // previous-iteration consumers done

        // xjs tile (coalesced)
        for (int idx = tid; idx < 64 * 12; idx += 256)
            sm[OFF_XJS + idx] = x[j0 * 12 + idx];
        // EinT rows 4..83 = h_concat[j] (coalesced via transposed g_hcT)
        for (int idx = tid; idx < 80 * 64; idx += 256) {
            int t = idx >> 6, jj = idx & 63;
            sm[OFF_EINT + (4 + t) * 64 + jj] = g_hcT[t * NN + j0 + jj];
        }
        __syncthreads();

        // EinT rows 0..3 = per-head sq norms ||x[j,h]-x[i,h]||^2 (256 = 64*4 threads)
        {
            int jj = tid >> 2, hh = tid & 3;
            float s = 0.0f;
#pragma unroll
            for (int d = 0; d < DDIM; d++) {
                float df = sm[OFF_XJS + jj * 12 + hh * 3 + d] - sm[OFF_XI + hh * 3 + d];
                s += df * df;
            }
            sm[OFF_EINT + hh * 64 + jj] = s;
        }
        __syncthreads();

        // phi_e layer 0: ZT = silu(EinT^T @ W0 + b0), stored [c][j]
        GEMM_T(OFF_EINT, OFF_W0, DE, OFF_B0, OFF_BUFA, -1);
        __syncthreads();

        // phi_e layer 1: MT = silu(Z @ W1 + b1) * off_diag, stored [c][j]
        const int maskj = (i >= j0 && i < j0 + 64) ? (i - j0) : -1;
        GEMM_T(OFF_BUFA, OFF_W1, HID, OFF_B1, OFF_BUFB, maskj);
        __syncthreads();

        // e_j = sigmoid(m_j . winf + binf) * off_diag
        if (tid < 64) {
            float a = binf_r;
#pragma unroll 8
            for (int c = 0; c < 64; c++)
                a += sm[OFF_BUFB + c * 64 + tid] * sm[OFF_WINF + c];
            sm[OFF_ES + tid] = (j0 + tid == i) ? 0.0f : sigmoidf_(a);
        }
        __syncthreads();

        // m_i accumulation: mi[c] += sum_j MT[c][j] * e[j]   (bank-skewed)
        if (tid < 64) {
            int c = tid;
#pragma unroll 8
            for (int j = 0; j < 64; j++) {
                int jj = (j + c) & 63;
                mi_acc += sm[OFF_BUFB + c * 64 + jj] * sm[OFF_ES + jj];
            }
        }

        // phi_x layer 0: P0T = silu(M @ Wx0 + bx0)   (bufB -> bufA, Z dead)
        GEMM_T(OFF_BUFB, OFF_WX0, HID, OFF_BX0, OFF_BUFA, -1);
        __syncthreads();

        // phi_x layer 1: P1T = silu(P0 @ Wx1 + bx1)  (bufA -> bufB, M dead)
        GEMM_T(OFF_BUFA, OFF_WX1, HID, OFF_BX1, OFF_BUFB, -1);
        __syncthreads();

        // phi_x final linear (64 -> 4) + normalized equivariant shift accumulation
        if (j0 + jj_me != i) {
            float px = sm[OFF_BX2 + hh_me];
#pragma unroll 8
            for (int c = 0; c < 64; c++)
                px += sm[OFF_BUFB + c * 64 + jj_me] * sm[OFF_WX2 + c * 4 + hh_me];
            float sq = sm[OFF_EINT + hh_me * 64 + jj_me];
            float nrm = sqrtf(sq) + 1.0f;      // sq>0 off-diagonal; sq==0 -> diff==0 anyway
            float coef = px / nrm;
            sh0 += coef * (sm[OFF_XJS + jj_me * 12 + hh_me * 3 + 0] - sm[OFF_XI + hh_me * 3 + 0]);
            sh1 += coef * (sm[OFF_XJS + jj_me * 12 + hh_me * 3 + 1] - sm[OFF_XI + hh_me * 3 + 1]);
            sh2 += coef * (sm[OFF_XJS + jj_me * 12 + hh_me * 3 + 2] - sm[OFF_XI + hh_me * 3 + 2]);
        }
    }

    // ---- epilogue ----
    __syncthreads();
    if (tid < 64) g_mi[i * 64 + tid] = mi_acc;
    sm[OFF_BUFA + tid * 3 + 0] = sh0;
    sm[OFF_BUFA + tid * 3 + 1] = sh1;
    sm[OFF_BUFA + tid * 3 + 2] = sh2;
    __syncthreads();
    if (tid < 12) {
        int hh = tid / 3, d = tid % 3;
        float s = 0.0f;
#pragma unroll 8
        for (int jj = 0; jj < 64; jj++)
            s += sm[OFF_BUFA + (hh * 64 + jj) * 3 + d];
        xout[i * 12 + hh * 3 + d] = sm[OFF_XI + hh * 3 + d] + s * (1.0f / 767.0f);
    }
}

// ---------------- kernel C: per-node phi_h + residual ----------------
__global__ void __launch_bounds__(64) node_kernel(
    const float* __restrict__ h,
    const float* __restrict__ wh0, const float* __restrict__ bh0,
    const float* __restrict__ wh1, const float* __restrict__ bh1,
    const float* __restrict__ wh2, const float* __restrict__ bh2,
    float* __restrict__ hout)
{
    __shared__ float in_s[128];
    __shared__ float z_s[64];
    int i = blockIdx.x, c = threadIdx.x;
    const float rs = rsqrtf(767.0f);

    in_s[c]      = g_mi[i * 64 + c] * rs;
    float hv     = h[i * 64 + c];
    in_s[64 + c] = hv;
    __syncthreads();

    float a = bh0[c];
#pragma unroll 8
    for (int k = 0; k < 128; k++) a += in_s[k] * wh0[k * 64 + c];
    z_s[c] = siluf_(a);
    __syncthreads();

    float a2 = bh1[c];
#pragma unroll 8
    for (int k = 0; k < 64; k++) a2 += z_s[k] * wh1[k * 64 + c];
    float z2 = siluf_(a2);
    __syncthreads();
    z_s[c] = z2;
    __syncthreads();

    float a3 = bh2[c];
#pragma unroll 8
    for (int k = 0; k < 64; k++) a3 += z_s[k] * wh2[k * 64 + c];
    hout[i * 64 + c] = hv + a3;
}

// ---------------- launch ----------------
extern "C" void kernel_launch(void* const* d_in, const int* in_sizes, int n_in,
                              void* d_out, int out_size)
{
    const float* x    = (const float*)d_in[0];
    const float* h    = (const float*)d_in[1];
    const float* w0   = (const float*)d_in[2];
    const float* b0   = (const float*)d_in[3];
    const float* w1   = (const float*)d_in[4];
    const float* b1   = (const float*)d_in[5];
    const float* winf = (const float*)d_in[6];
    const float* binf = (const float*)d_in[7];
    const float* wx0  = (const float*)d_in[8];
    const float* bx0  = (const float*)d_in[9];
    const float* wx1  = (const float*)d_in[10];
    const float* bx1  = (const float*)d_in[11];
    const float* wx2  = (const float*)d_in[12];
    const float* bx2  = (const float*)d_in[13];
    const float* wh0  = (const float*)d_in[14];
    const float* bh0  = (const float*)d_in[15];
    const float* wh1  = (const float*)d_in[16];
    const float* bh1  = (const float*)d_in[17];
    const float* wh2  = (const float*)d_in[18];
    const float* bh2  = (const float*)d_in[19];

    float* out  = (float*)d_out;
    float* xout = out;                       // [768,4,3]
    float* hout = out + NN * HH * DDIM;      // [768,64]

    cudaFuncSetAttribute(pair_kernel, cudaFuncAttributeMaxDynamicSharedMemorySize, SMEM_BYTES);

    prep_kernel<<<NN, 80>>>(x, h);
    pair_kernel<<<NN, 256, SMEM_BYTES>>>(x, w0, b0, w1, b1, winf, binf,
                                         wx0, bx0, wx1, bx1, wx2, bx2, xout);
    node_kernel<<<NN, 64>>>(h, wh0, bh0, wh1, bh1, wh2, bh2, hout);
}